// round 1
// baseline (speedup 1.0000x reference)
#include <cuda_runtime.h>
#include <math.h>

#define Bn 64
#define Cn 3
#define Hn 512
#define Wn 512
#define CUT_H 256
#define CUT_W 256

struct __align__(16) BatchParams {
    float m00, m01, m10, m11;   // affine: gx = m00*gx0 + m01*gy0 + tx
    float tx, ty;
    float bb, cc, ss;
    int   flip, cut, y0, x0;
};

__device__ BatchParams g_params[Bn];

__global__ void precompute_params_kernel(
    const float* __restrict__ u_angle, const float* __restrict__ u_scale,
    const float* __restrict__ u_trans, const float* __restrict__ u_bright,
    const float* __restrict__ u_contrast, const float* __restrict__ u_sat,
    const int* __restrict__ m_flip, const int* __restrict__ m_rot,
    const int* __restrict__ m_scale, const int* __restrict__ m_trans,
    const int* __restrict__ m_bright, const int* __restrict__ m_contrast,
    const int* __restrict__ m_sat, const int* __restrict__ m_cut,
    const int* __restrict__ y0, const int* __restrict__ x0)
{
    int b = threadIdx.x;
    if (b >= Bn) return;
    const float PI = 3.14159265358979323846f;
    float angle = (m_rot[b] > 0) ? (u_angle[b] * 2.0f - 1.0f) * PI : 0.0f;
    float sc    = (m_scale[b] > 0) ? (u_scale[b] * 2.0f - 1.0f) * 0.2f + 1.0f : 1.0f;
    float tr    = (m_trans[b] > 0) ? (u_trans[b] * 2.0f - 1.0f) * 0.125f : 0.0f;
    float ca = cosf(angle);
    float sa = sinf(angle);
    BatchParams p;
    p.m00 = sc * ca;  p.m01 = -sc * sa;
    p.m10 = sc * sa;  p.m11 =  sc * ca;
    p.tx = tr; p.ty = tr;
    p.bb = (m_bright[b]   > 0) ? u_bright[b] * 0.2f   : 0.0f;
    p.cc = (m_contrast[b] > 0) ? u_contrast[b] + 0.5f : 1.0f;
    p.ss = (m_sat[b]      > 0) ? u_sat[b] * 2.0f      : 1.0f;
    p.flip = m_flip[b];
    p.cut  = m_cut[b];
    p.y0 = y0[b];
    p.x0 = x0[b];
    g_params[b] = p;
}

__device__ __forceinline__ float reflect_coord(float v, float size) {
    v = fabsf(v + 0.5f);
    v = fmodf(v, 2.0f * size);
    v = fminf(v, 2.0f * size - v);
    return fminf(fmaxf(v - 0.5f, 0.0f), size - 1.0f);
}

__device__ __forceinline__ float clip1(float v) {
    return fminf(fmaxf(v, -1.0f), 1.0f);
}

__global__ void __launch_bounds__(256) augment_kernel(
    const float* __restrict__ images,
    const float* __restrict__ noise,
    float* __restrict__ out)
{
    const int b   = blockIdx.y;
    const int pix = blockIdx.x * blockDim.x + threadIdx.x;
    const int y = pix >> 9;          // /512
    const int x = pix & (Wn - 1);    // %512

    const BatchParams p = g_params[b];

    const size_t img_base = (size_t)b * (Cn * Hn * Wn);
    const size_t out_idx  = img_base + (size_t)y * Wn + x;

    // Cutout: reference computes full pipeline then overwrites with noise;
    // output-identical to copying noise directly.
    const bool incut = (p.cut > 0) &&
                       (y >= p.y0) && (y < p.y0 + CUT_H) &&
                       (x >= p.x0) && (x < p.x0 + CUT_W);
    if (incut) {
        #pragma unroll
        for (int c = 0; c < Cn; c++) {
            out[out_idx + (size_t)c * (Hn * Wn)] =
                noise[out_idx + (size_t)c * (Hn * Wn)];
        }
        return;
    }

    // linspace(-1,1,N): -1 + i*2/(N-1)
    const float gx0 = fmaf((float)x, 2.0f / (Wn - 1), -1.0f);
    const float gy0 = fmaf((float)y, 2.0f / (Hn - 1), -1.0f);

    const float gx = p.m00 * gx0 + p.m01 * gy0 + p.tx;
    const float gy = p.m10 * gx0 + p.m11 * gy0 + p.ty;

    float fx = ((gx + 1.0f) * (float)Wn - 1.0f) * 0.5f;
    float fy = ((gy + 1.0f) * (float)Hn - 1.0f) * 0.5f;
    fx = reflect_coord(fx, (float)Wn);
    fy = reflect_coord(fy, (float)Hn);

    const float x0f = floorf(fx);
    const float y0f = floorf(fy);
    const float wx = fx - x0f;
    const float wy = fy - y0f;

    int xi0 = (int)x0f;                   // reflect output in [0, W-1]
    int xi1 = min(xi0 + 1, Wn - 1);
    int yi0 = (int)y0f;
    int yi1 = min(yi0 + 1, Hn - 1);

    // Horizontal flip is applied to the source image before sampling:
    // sampling flipped image at column xi == original image at (W-1-xi).
    if (p.flip > 0) {
        xi0 = (Wn - 1) - xi0;
        xi1 = (Wn - 1) - xi1;
    }

    const int o00 = yi0 * Wn + xi0;
    const int o01 = yi0 * Wn + xi1;
    const int o10 = yi1 * Wn + xi0;
    const int o11 = yi1 * Wn + xi1;

    float r[Cn];
    #pragma unroll
    for (int c = 0; c < Cn; c++) {
        const float* ic = images + img_base + (size_t)c * (Hn * Wn);
        const float v00 = __ldg(ic + o00);
        const float v01 = __ldg(ic + o01);
        const float v10 = __ldg(ic + o10);
        const float v11 = __ldg(ic + o11);
        const float top = v00 + wx * (v01 - v00);
        const float bot = v10 + wx * (v11 - v10);
        r[c] = top + wy * (bot - top);
    }

    #pragma unroll
    for (int c = 0; c < Cn; c++) r[c] = clip1(r[c] + p.bb);
    #pragma unroll
    for (int c = 0; c < Cn; c++) r[c] = clip1(r[c] * p.cc);

    const float gray = (r[0] + r[1] + r[2]) / 3.0f;
    #pragma unroll
    for (int c = 0; c < Cn; c++) r[c] = clip1(gray + p.ss * (r[c] - gray));

    #pragma unroll
    for (int c = 0; c < Cn; c++) {
        out[out_idx + (size_t)c * (Hn * Wn)] = r[c];
    }
}

extern "C" void kernel_launch(void* const* d_in, const int* in_sizes, int n_in,
                              void* d_out, int out_size) {
    const float* images     = (const float*)d_in[0];
    const float* u_angle    = (const float*)d_in[1];
    const float* u_scale    = (const float*)d_in[2];
    const float* u_trans    = (const float*)d_in[3];
    const float* u_bright   = (const float*)d_in[4];
    const float* u_contrast = (const float*)d_in[5];
    const float* u_sat      = (const float*)d_in[6];
    const float* noise      = (const float*)d_in[7];
    const int*   m_flip     = (const int*)d_in[8];
    const int*   m_rot      = (const int*)d_in[9];
    const int*   m_scale    = (const int*)d_in[10];
    const int*   m_trans    = (const int*)d_in[11];
    const int*   m_bright   = (const int*)d_in[12];
    const int*   m_contrast = (const int*)d_in[13];
    const int*   m_sat      = (const int*)d_in[14];
    const int*   m_cut      = (const int*)d_in[15];
    const int*   y0         = (const int*)d_in[16];
    const int*   x0         = (const int*)d_in[17];
    float* out = (float*)d_out;

    precompute_params_kernel<<<1, 64>>>(
        u_angle, u_scale, u_trans, u_bright, u_contrast, u_sat,
        m_flip, m_rot, m_scale, m_trans, m_bright, m_contrast,
        m_sat, m_cut, y0, x0);

    dim3 block(256);
    dim3 grid((Hn * Wn) / 256, Bn);
    augment_kernel<<<grid, block>>>(images, noise, out);
}

// round 2
// speedup vs baseline: 1.2341x; 1.2341x over previous
#include <cuda_runtime.h>
#include <math.h>

#define Bn 64
#define Cn 3
#define Hn 512
#define Wn 512
#define CUT_H 256
#define CUT_W 256

struct __align__(16) BatchParams {
    float m00, m01, m10, m11;   // affine: gx = m00*gx0 + m01*gy0 + tx
    float tx, ty;
    float bb, cc, ss;
    int   flip, cut, y0, x0;
};

__device__ BatchParams g_params[Bn];

__global__ void precompute_params_kernel(
    const float* __restrict__ u_angle, const float* __restrict__ u_scale,
    const float* __restrict__ u_trans, const float* __restrict__ u_bright,
    const float* __restrict__ u_contrast, const float* __restrict__ u_sat,
    const int* __restrict__ m_flip, const int* __restrict__ m_rot,
    const int* __restrict__ m_scale, const int* __restrict__ m_trans,
    const int* __restrict__ m_bright, const int* __restrict__ m_contrast,
    const int* __restrict__ m_sat, const int* __restrict__ m_cut,
    const int* __restrict__ y0, const int* __restrict__ x0)
{
    int b = threadIdx.x;
    if (b >= Bn) return;
    const float PI = 3.14159265358979323846f;
    float angle = (m_rot[b] > 0) ? (u_angle[b] * 2.0f - 1.0f) * PI : 0.0f;
    float sc    = (m_scale[b] > 0) ? (u_scale[b] * 2.0f - 1.0f) * 0.2f + 1.0f : 1.0f;
    float tr    = (m_trans[b] > 0) ? (u_trans[b] * 2.0f - 1.0f) * 0.125f : 0.0f;
    float ca = cosf(angle);
    float sa = sinf(angle);
    BatchParams p;
    p.m00 = sc * ca;  p.m01 = -sc * sa;
    p.m10 = sc * sa;  p.m11 =  sc * ca;
    p.tx = tr; p.ty = tr;
    p.bb = (m_bright[b]   > 0) ? u_bright[b] * 0.2f   : 0.0f;
    p.cc = (m_contrast[b] > 0) ? u_contrast[b] + 0.5f : 1.0f;
    p.ss = (m_sat[b]      > 0) ? u_sat[b] * 2.0f      : 1.0f;
    p.flip = m_flip[b];
    p.cut  = m_cut[b];
    p.y0 = y0[b];
    p.x0 = x0[b];
    g_params[b] = p;
}

__device__ __forceinline__ float reflect_coord(float v, float size) {
    v = fabsf(v + 0.5f);
    v = fmodf(v, 2.0f * size);
    v = fminf(v, 2.0f * size - v);
    return fminf(fmaxf(v - 0.5f, 0.0f), size - 1.0f);
}

__device__ __forceinline__ float clip1(float v) {
    return fminf(fmaxf(v, -1.0f), 1.0f);
}

__global__ void __launch_bounds__(256) augment_kernel(
    const float* __restrict__ images,
    const float* __restrict__ noise,
    float* __restrict__ out)
{
    const int b = blockIdx.y;
    const BatchParams p = g_params[b];

    // ---- angle-adaptive thread -> pixel mapping (block-uniform branch) ----
    // Row-major warps are optimal when source rows stay ~constant across the
    // warp (|dfy/dx| = |m10| small). For strong rotation, map each warp to an
    // 8x4 pixel tile so the gather footprint is compact in 2D.
    int x, y;
    if (fabsf(p.m10) > 0.30f) {
        // Block covers a 32x8 tile. 16 tiles across x, 64 down y (512x512).
        const int t    = blockIdx.x;
        const int tx   = t & 15;       // tile x: 0..15
        const int ty   = t >> 4;       // tile y: 0..63
        const int warp = threadIdx.x >> 5;
        const int lane = threadIdx.x & 31;
        x = (tx << 5) + ((warp & 3) << 3) + (lane & 7);   // warp tile 8 wide
        y = (ty << 3) + ((warp >> 2) << 2) + (lane >> 3); // warp tile 4 tall
    } else {
        const int pix = blockIdx.x * 256 + threadIdx.x;
        y = pix >> 9;
        x = pix & (Wn - 1);
    }

    const size_t img_base = (size_t)b * (Cn * Hn * Wn);
    const size_t out_idx  = img_base + (size_t)y * Wn + x;

    // Cutout: output-identical to copying noise directly.
    const bool incut = (p.cut > 0) &&
                       (y >= p.y0) && (y < p.y0 + CUT_H) &&
                       (x >= p.x0) && (x < p.x0 + CUT_W);
    if (incut) {
        #pragma unroll
        for (int c = 0; c < Cn; c++) {
            out[out_idx + (size_t)c * (Hn * Wn)] =
                noise[out_idx + (size_t)c * (Hn * Wn)];
        }
        return;
    }

    const float gx0 = fmaf((float)x, 2.0f / (Wn - 1), -1.0f);
    const float gy0 = fmaf((float)y, 2.0f / (Hn - 1), -1.0f);

    const float gx = p.m00 * gx0 + p.m01 * gy0 + p.tx;
    const float gy = p.m10 * gx0 + p.m11 * gy0 + p.ty;

    float fx = ((gx + 1.0f) * (float)Wn - 1.0f) * 0.5f;
    float fy = ((gy + 1.0f) * (float)Hn - 1.0f) * 0.5f;
    fx = reflect_coord(fx, (float)Wn);
    fy = reflect_coord(fy, (float)Hn);

    const float x0f = floorf(fx);
    const float y0f = floorf(fy);
    const float wx = fx - x0f;
    const float wy = fy - y0f;

    int xi0 = (int)x0f;
    int xi1 = min(xi0 + 1, Wn - 1);
    int yi0 = (int)y0f;
    int yi1 = min(yi0 + 1, Hn - 1);

    // Horizontal flip folded into the gather index.
    if (p.flip > 0) {
        xi0 = (Wn - 1) - xi0;
        xi1 = (Wn - 1) - xi1;
    }

    const int o00 = yi0 * Wn + xi0;
    const int o01 = yi0 * Wn + xi1;
    const int o10 = yi1 * Wn + xi0;
    const int o11 = yi1 * Wn + xi1;

    // Batch ALL tap loads first for maximum memory-level parallelism.
    float v00[Cn], v01[Cn], v10[Cn], v11[Cn];
    #pragma unroll
    for (int c = 0; c < Cn; c++) {
        const float* ic = images + img_base + (size_t)c * (Hn * Wn);
        v00[c] = __ldg(ic + o00);
        v01[c] = __ldg(ic + o01);
        v10[c] = __ldg(ic + o10);
        v11[c] = __ldg(ic + o11);
    }

    float r[Cn];
    #pragma unroll
    for (int c = 0; c < Cn; c++) {
        const float top = v00[c] + wx * (v01[c] - v00[c]);
        const float bot = v10[c] + wx * (v11[c] - v10[c]);
        r[c] = top + wy * (bot - top);
    }

    #pragma unroll
    for (int c = 0; c < Cn; c++) r[c] = clip1(r[c] + p.bb);
    #pragma unroll
    for (int c = 0; c < Cn; c++) r[c] = clip1(r[c] * p.cc);

    const float gray = (r[0] + r[1] + r[2]) / 3.0f;
    #pragma unroll
    for (int c = 0; c < Cn; c++) r[c] = clip1(gray + p.ss * (r[c] - gray));

    #pragma unroll
    for (int c = 0; c < Cn; c++) {
        out[out_idx + (size_t)c * (Hn * Wn)] = r[c];
    }
}

extern "C" void kernel_launch(void* const* d_in, const int* in_sizes, int n_in,
                              void* d_out, int out_size) {
    const float* images     = (const float*)d_in[0];
    const float* u_angle    = (const float*)d_in[1];
    const float* u_scale    = (const float*)d_in[2];
    const float* u_trans    = (const float*)d_in[3];
    const float* u_bright   = (const float*)d_in[4];
    const float* u_contrast = (const float*)d_in[5];
    const float* u_sat      = (const float*)d_in[6];
    const float* noise      = (const float*)d_in[7];
    const int*   m_flip     = (const int*)d_in[8];
    const int*   m_rot      = (const int*)d_in[9];
    const int*   m_scale    = (const int*)d_in[10];
    const int*   m_trans    = (const int*)d_in[11];
    const int*   m_bright   = (const int*)d_in[12];
    const int*   m_contrast = (const int*)d_in[13];
    const int*   m_sat      = (const int*)d_in[14];
    const int*   m_cut      = (const int*)d_in[15];
    const int*   y0         = (const int*)d_in[16];
    const int*   x0         = (const int*)d_in[17];
    float* out = (float*)d_out;

    precompute_params_kernel<<<1, 64>>>(
        u_angle, u_scale, u_trans, u_bright, u_contrast, u_sat,
        m_flip, m_rot, m_scale, m_trans, m_bright, m_contrast,
        m_sat, m_cut, y0, x0);

    dim3 block(256);
    dim3 grid((Hn * Wn) / 256, Bn);
    augment_kernel<<<grid, block>>>(images, noise, out);
}